// round 4
// baseline (speedup 1.0000x reference)
#include <cuda_runtime.h>
#include <math.h>

// Problem constants (fixed by the reference)
#define BATCH   16
#define LQ      2048
#define LK      2048
#define DIM     128
#define BM      128     // query rows per CTA
#define BKT     64      // keys per tile
#define NTHR    256

#define QS_STRIDE 132   // padded row stride (floats) for Q tile
#define KS_STRIDE 128   // K tile stored with XOR chunk swizzle, no pad
#define VS_STRIDE 132
#define ES_STRIDE 68

// smem: pass1 uses Qs[BM][QS_STRIDE] + Ks[BKT][KS_STRIDE]
//       pass2 reuses the same region as Vs[BKT][VS_STRIDE] + Es[BM][ES_STRIDE]
#define SMEM_FLOATS (BM*QS_STRIDE + BKT*KS_STRIDE)   // 25088 floats = 100352 B
#define SMEM_BYTES  (SMEM_FLOATS * 4)

// 256 MB scratch for the S = -(QK^T)*scale scores (static __device__ array:
// the sanctioned no-cudaMalloc scratch mechanism). Each thread re-reads only
// elements it wrote itself in pass 1, so no cross-thread visibility issue.
__device__ float g_S[(size_t)BATCH * LQ * LK];

// ---- Blackwell packed f32x2 FMA (ptxas never emits this from C++) ----
#define FFMA2(acc, a, b) \
    asm("fma.rn.f32x2 %0, %1, %2, %0;" : "+l"(acc) : "l"(a), "l"(b))

__device__ __forceinline__ unsigned long long pack2(float lo, float hi) {
    unsigned long long r;
    asm("mov.b64 %0, {%1, %2};" : "=l"(r)
        : "r"(__float_as_uint(lo)), "r"(__float_as_uint(hi)));
    return r;
}
__device__ __forceinline__ void unpack2(unsigned long long v, float& lo, float& hi) {
    unsigned int a, b;
    asm("mov.b64 {%0, %1}, %2;" : "=r"(a), "=r"(b) : "l"(v));
    lo = __uint_as_float(a); hi = __uint_as_float(b);
}

// XOR swizzle for the K tile: 16B-chunk index XOR'd with row so a warp
// storing one full row stays conflict-free and column-direction reads
// (16 lanes stepping rows by 4) mostly hit distinct banks.
__device__ __forceinline__ int ksw(int row, int chunk) {
    return row * KS_STRIDE + (((chunk) ^ (row & 31)) << 2);
}

#define TILE_LD_ITERS ((BKT * DIM) / (NTHR * 4))   // 8 float4 per thread per tile

__global__ void __launch_bounds__(NTHR, 1)
attn_neg2sm_kernel(const float* __restrict__ Qp, const float* __restrict__ Kp,
                   const float* __restrict__ Vp, const float* __restrict__ scale_p,
                   const float* __restrict__ Gp, float* __restrict__ Op)
{
    extern __shared__ float smem[];
    float* Qs = smem;                       // pass1: [BM][QS_STRIDE]
    float* Ks = Qs + BM * QS_STRIDE;        // pass1: [BKT][KS_STRIDE] (swizzled)
    float* Vs = smem;                       // pass2: [BKT][VS_STRIDE]
    float* Es = Vs + BKT * VS_STRIDE;       // pass2: [BM][ES_STRIDE]

    const int b   = blockIdx.y;
    const int q0  = blockIdx.x * BM;
    const int tid = threadIdx.x;
    const int ty  = tid >> 4;   // 0..15 -> 8 query rows each
    const int tx  = tid & 15;   // 0..15 -> 4 key cols (pass1/E) / 8 d cols (PV)
    const float scale = *scale_p;

    const float* Qg = Qp + ((size_t)b * LQ + q0) * DIM;
    const float* Kg = Kp + (size_t)b * LK * DIM;
    const float* Vg = Vp + (size_t)b * LK * DIM;
    const float* Grow = Gp + ((size_t)b * LQ + q0) * LK;
    float* Srow = g_S + ((size_t)b * LQ + q0) * LK;

    // per-thread tile-load coordinates (8 float4 chunks, fixed across tiles)
    int ld_r[TILE_LD_ITERS], ld_c[TILE_LD_ITERS];
    #pragma unroll
    for (int it = 0; it < TILE_LD_ITERS; ++it) {
        int idx = tid * 4 + it * NTHR * 4;
        ld_r[it] = idx >> 7; ld_c[it] = idx & 127;
    }

    // ---- load Q tile (once) ----
    #pragma unroll
    for (int it = 0; it < (BM * DIM) / (NTHR * 4); ++it) {   // 16 iters
        int idx = tid * 4 + it * NTHR * 4;
        int r = idx >> 7, c = idx & 127;
        *(float4*)(Qs + r * QS_STRIDE + c) = *(const float4*)(Qg + (size_t)r * DIM + c);
    }

    float m1[8], Z1[8];
    #pragma unroll
    for (int i = 0; i < 8; i++) { m1[i] = -INFINITY; Z1[i] = 0.f; }

    // ================= pass 1: S = -(QK^T)*scale -> scratch; row max + Z1 ======
    // double-buffered: tile k+1 prefetched into kbuf while computing tile k
    float4 kbuf[TILE_LD_ITERS];
    #pragma unroll
    for (int it = 0; it < TILE_LD_ITERS; ++it)
        kbuf[it] = *(const float4*)(Kg + (size_t)ld_r[it] * DIM + ld_c[it]);
    #pragma unroll
    for (int it = 0; it < TILE_LD_ITERS; ++it)
        *(float4*)(Ks + ksw(ld_r[it], ld_c[it] >> 2)) = kbuf[it];   // own slots, no sync needed

    for (int k0 = 0; k0 < LK; k0 += BKT) {
        __syncthreads();    // Ks (and, first iter, Qs) stores visible

        const bool has_next = (k0 + BKT) < LK;
        if (has_next) {
            const float* Kn = Kg + (size_t)(k0 + BKT) * DIM;
            #pragma unroll
            for (int it = 0; it < TILE_LD_ITERS; ++it)
                kbuf[it] = *(const float4*)(Kn + (size_t)ld_r[it] * DIM + ld_c[it]);
        }

        // packed accumulators: acc2[i][j] holds 2 partial sums (even/odd d)
        unsigned long long acc2[8][4];
        #pragma unroll
        for (int i = 0; i < 8; i++)
            #pragma unroll
            for (int j = 0; j < 4; j++) acc2[i][j] = 0ull;

        #pragma unroll 4
        for (int d = 0; d < DIM; d += 4) {
            ulonglong2 a2[8], b2[4];
            #pragma unroll
            for (int j = 0; j < 4; j++)
                b2[j] = *(const ulonglong2*)(Ks + ksw(tx*4+j, d >> 2));
            #pragma unroll
            for (int i = 0; i < 8; i++)
                a2[i] = *(const ulonglong2*)(Qs + (ty*8+i)*QS_STRIDE + d);
            #pragma unroll
            for (int i = 0; i < 8; i++)
                #pragma unroll
                for (int j = 0; j < 4; j++) {
                    FFMA2(acc2[i][j], a2[i].x, b2[j].x);
                    FFMA2(acc2[i][j], a2[i].y, b2[j].y);
                }
        }

        // online softmax stats + spill S tile to scratch
        #pragma unroll
        for (int i = 0; i < 8; i++) {
            float s0[4], tm = -INFINITY;
            #pragma unroll
            for (int j = 0; j < 4; j++) {
                float lo, hi; unpack2(acc2[i][j], lo, hi);
                s0[j] = -(lo + hi) * scale;
                tm = fmaxf(tm, s0[j]);
            }
            *(float4*)(Srow + (size_t)(ty*8+i) * LK + k0 + tx*4)
                = make_float4(s0[0], s0[1], s0[2], s0[3]);
            #pragma unroll
            for (int off = 8; off > 0; off >>= 1)
                tm = fmaxf(tm, __shfl_xor_sync(0xffffffffu, tm, off));
            float nm = fmaxf(m1[i], tm);
            float ss = 0.f;
            #pragma unroll
            for (int j = 0; j < 4; j++) ss += __expf(s0[j] - nm);
            #pragma unroll
            for (int off = 8; off > 0; off >>= 1)
                ss += __shfl_xor_sync(0xffffffffu, ss, off);
            Z1[i] = Z1[i] * __expf(m1[i] - nm) + ss;
            m1[i] = nm;
        }

        __syncthreads();    // all Ks/Qs reads of this tile done
        if (has_next) {
            #pragma unroll
            for (int it = 0; it < TILE_LD_ITERS; ++it)
                *(float4*)(Ks + ksw(ld_r[it], ld_c[it] >> 2)) = kbuf[it];
        }
    }

    float invZ1[8];
    #pragma unroll
    for (int i = 0; i < 8; i++) invZ1[i] = 1.f / Z1[i];

    // ================= pass 2: E = exp(-g*p), Z2, O = E V =================
    // o2[i][jp] packs output d-columns (tx*8 + 2*jp, tx*8 + 2*jp + 1)
    unsigned long long o2[8][4];
    #pragma unroll
    for (int i = 0; i < 8; i++)
        #pragma unroll
        for (int j = 0; j < 4; j++) o2[i][j] = 0ull;
    float Z2[8];
    #pragma unroll
    for (int i = 0; i < 8; i++) Z2[i] = 0.f;

    // V tile 0: pass-1's trailing barrier already closed all Qs-region reads,
    // so overwriting Vs (= Qs alias) is safe.
    float4 vbuf[TILE_LD_ITERS];
    #pragma unroll
    for (int it = 0; it < TILE_LD_ITERS; ++it)
        vbuf[it] = *(const float4*)(Vg + (size_t)ld_r[it] * DIM + ld_c[it]);
    #pragma unroll
    for (int it = 0; it < TILE_LD_ITERS; ++it)
        *(float4*)(Vs + ld_r[it] * VS_STRIDE + ld_c[it]) = vbuf[it];

    for (int k0 = 0; k0 < LK; k0 += BKT) {
        const bool has_next = (k0 + BKT) < LK;
        if (has_next) {
            const float* Vn = Vg + (size_t)(k0 + BKT) * DIM;
            #pragma unroll
            for (int it = 0; it < TILE_LD_ITERS; ++it)
                vbuf[it] = *(const float4*)(Vn + (size_t)ld_r[it] * DIM + ld_c[it]);
        }

        // E tile: p = exp(S - m1)/Z1 ; E = exp(-g*p)   (T = -g*p in (-1,0])
        #pragma unroll
        for (int i = 0; i < 8; i++) {
            int r = ty * 8 + i;
            float4 sv = *(const float4*)(Srow + (size_t)r * LK + k0 + tx*4);
            float4 gv = *(const float4*)(Grow + (size_t)r * LK + k0 + tx*4);
            float s[4] = {sv.x, sv.y, sv.z, sv.w};
            float g[4] = {gv.x, gv.y, gv.z, gv.w};
            float e[4];
            #pragma unroll
            for (int j = 0; j < 4; j++) {
                float p = __expf(s[j] - m1[i]) * invZ1[i];
                e[j] = __expf(-g[j] * p);
                Z2[i] += e[j];
            }
            *(float4*)(Es + r * ES_STRIDE + tx * 4) = make_float4(e[0], e[1], e[2], e[3]);
        }
        __syncthreads();    // Vs stores + Es writes visible

        // PV: o[i][:] += E[row_i][k] * V[k][:]   (8 rows x 8 cols per thread, f32x2)
        #pragma unroll 2
        for (int k = 0; k < BKT; k += 4) {
            float4 e4[8];
            #pragma unroll
            for (int i = 0; i < 8; i++) e4[i] = *(const float4*)(Es + (ty*8+i)*ES_STRIDE + k);
            #pragma unroll
            for (int kk = 0; kk < 4; kk++) {
                ulonglong2 v0 = *(const ulonglong2*)(Vs + (k + kk) * VS_STRIDE + tx * 8);
                ulonglong2 v1 = *(const ulonglong2*)(Vs + (k + kk) * VS_STRIDE + tx * 8 + 4);
                #pragma unroll
                for (int i = 0; i < 8; i++) {
                    float e = (kk == 0) ? e4[i].x : (kk == 1) ? e4[i].y
                            : (kk == 2) ? e4[i].z : e4[i].w;
                    unsigned long long ee = pack2(e, e);
                    FFMA2(o2[i][0], ee, v0.x);
                    FFMA2(o2[i][1], ee, v0.y);
                    FFMA2(o2[i][2], ee, v1.x);
                    FFMA2(o2[i][3], ee, v1.y);
                }
            }
        }

        __syncthreads();    // all Vs/Es reads of this tile done
        if (has_next) {
            #pragma unroll
            for (int it = 0; it < TILE_LD_ITERS; ++it)
                *(float4*)(Vs + ld_r[it] * VS_STRIDE + ld_c[it]) = vbuf[it];
        }
    }

    // ---- finalize: reduce Z2 across tx half-warp, write O / Z2 ----
    #pragma unroll
    for (int i = 0; i < 8; i++) {
        float z = Z2[i];
        #pragma unroll
        for (int off = 8; off > 0; off >>= 1)
            z += __shfl_xor_sync(0xffffffffu, z, off);
        float rz = 1.f / z;
        float ov[8];
        #pragma unroll
        for (int jp = 0; jp < 4; jp++) unpack2(o2[i][jp], ov[2*jp], ov[2*jp+1]);
        float* outr = Op + ((size_t)b * LQ + q0 + ty * 8 + i) * DIM + tx * 8;
        *(float4*)(outr)     = make_float4(ov[0]*rz, ov[1]*rz, ov[2]*rz, ov[3]*rz);
        *(float4*)(outr + 4) = make_float4(ov[4]*rz, ov[5]*rz, ov[6]*rz, ov[7]*rz);
    }
}

extern "C" void kernel_launch(void* const* d_in, const int* in_sizes, int n_in,
                              void* d_out, int out_size)
{
    const float* Q  = (const float*)d_in[0];
    const float* K  = (const float*)d_in[1];
    const float* V  = (const float*)d_in[2];
    const float* sc = (const float*)d_in[3];
    const float* G  = (const float*)d_in[4];
    float* Out = (float*)d_out;

    // >48KB dynamic smem: idempotent host-side attribute set (not a stream op)
    cudaFuncSetAttribute(attn_neg2sm_kernel,
                         cudaFuncAttributeMaxDynamicSharedMemorySize, SMEM_BYTES);

    dim3 grid(LQ / BM, BATCH);   // 16 x 16 = 256 CTAs
    attn_neg2sm_kernel<<<grid, NTHR, SMEM_BYTES>>>(Q, K, V, sc, G, Out);
}

// round 7
// speedup vs baseline: 1.9159x; 1.9159x over previous
#include <cuda_runtime.h>
#include <cuda_bf16.h>
#include <math.h>

// Problem constants (fixed by the reference)
#define BATCH   16
#define LQ      2048
#define LK      2048
#define DIM     128
#define BM      128     // query rows per CTA
#define BKT     64      // keys per tile
#define NTHR    256

// ---- pass-2 (SIMT PV) smem strides, unchanged from the verified kernel ----
#define VS_STRIDE 132
#define ES_STRIDE 68

// ---- smem layout (bytes) ----
// [0,1024):       row_m[128], row_z[128]  (persist across passes)
// [1024, ...):    union:
//    pass1: Qb bf16[128][128] (32768 B) + Kb bf16[64][128] (16384 B)
//    pass2: Vs f32[64][132] (33792 B) + Es f32[128][68] (34816 B)
#define SM_MZ     0
#define SM_UNION  1024
#define SM_QB     (SM_UNION)
#define SM_KB     (SM_UNION + 32768)
#define SM_VS     (SM_UNION)
#define SM_ES     (SM_UNION + 64*VS_STRIDE*4)
#define SMEM_BYTES (SM_UNION + 64*VS_STRIDE*4 + 128*ES_STRIDE*4)   // 69632

// 256 MB scratch for S = -(QK^T)*scale (static __device__: sanctioned no-alloc
// scratch). Written in pass 1, read in pass 2 by other threads of the SAME CTA;
// __syncthreads() makes CTA-prior global writes visible block-wide.
__device__ float g_S[(size_t)BATCH * LQ * LK];

// ---- Blackwell packed f32x2 FMA (pass-2 PV; ptxas never emits from C++) ----
#define FFMA2(acc, a, b) \
    asm("fma.rn.f32x2 %0, %1, %2, %0;" : "+l"(acc) : "l"(a), "l"(b))

__device__ __forceinline__ unsigned long long pack2(float lo, float hi) {
    unsigned long long r;
    asm("mov.b64 %0, {%1, %2};" : "=l"(r)
        : "r"(__float_as_uint(lo)), "r"(__float_as_uint(hi)));
    return r;
}
__device__ __forceinline__ void unpack2(unsigned long long v, float& lo, float& hi) {
    unsigned int a, b;
    asm("mov.b64 {%0, %1}, %2;" : "=r"(a), "=r"(b) : "l"(v));
    lo = __uint_as_float(a); hi = __uint_as_float(b);
}

// ---- bf16 tensor-core helpers (pass 1) ----
__device__ __forceinline__ unsigned smem_u32(const void* p) {
    unsigned r;
    asm("{ .reg .u64 t; cvta.to.shared.u64 t, %1; cvt.u32.u64 %0, t; }"
        : "=r"(r) : "l"(p));
    return r;
}
// pack {lo,hi} fp32 -> bf16x2 (lo in low halfword)
__device__ __forceinline__ unsigned cvt2bf(float lo, float hi) {
    unsigned r;
    asm("cvt.rn.bf16x2.f32 %0, %1, %2;" : "=r"(r) : "f"(hi), "f"(lo));
    return r;
}
#define LDSM_X4(r0,r1,r2,r3,addr) \
    asm volatile("ldmatrix.sync.aligned.m8n8.x4.shared.b16 {%0,%1,%2,%3}, [%4];" \
        : "=r"(r0),"=r"(r1),"=r"(r2),"=r"(r3) : "r"(addr))
#define MMA_BF16(c,a0,a1,a2,a3,b0,b1) \
    asm volatile("mma.sync.aligned.m16n8k16.row.col.f32.bf16.bf16.f32 " \
        "{%0,%1,%2,%3},{%4,%5,%6,%7},{%8,%9},{%0,%1,%2,%3};" \
        : "+f"((c)[0]),"+f"((c)[1]),"+f"((c)[2]),"+f"((c)[3]) \
        : "r"(a0),"r"(a1),"r"(a2),"r"(a3),"r"(b0),"r"(b1))

#define TILE_LD_ITERS ((BKT * DIM) / (NTHR * 4))   // 8 float4/thread (pass-2 V)

__global__ void __launch_bounds__(NTHR, 1)
attn_neg2sm_kernel(const float* __restrict__ Qp, const float* __restrict__ Kp,
                   const float* __restrict__ Vp, const float* __restrict__ scale_p,
                   const float* __restrict__ Gp, float* __restrict__ Op)
{
    extern __shared__ char smem[];
    float* row_m = (float*)(smem + SM_MZ);
    float* row_z = row_m + 128;
    float* Vs = (float*)(smem + SM_VS);
    float* Es = (float*)(smem + SM_ES);

    const int b    = blockIdx.y;
    const int q0   = blockIdx.x * BM;
    const int tid  = threadIdx.x;
    const int lane = tid & 31;
    const int w    = tid >> 5;          // warp 0..7, owns Q rows 16w..16w+15
    const float scale = *scale_p;

    const float* Qg = Qp + ((size_t)b * LQ + q0) * DIM;
    const float* Kg = Kp + (size_t)b * LK * DIM;
    const float* Vg = Vp + (size_t)b * LK * DIM;
    const float* Grow = Gp + ((size_t)b * LQ + q0) * LK;
    float* Srow = g_S + ((size_t)b * LQ + q0) * LK;

    const unsigned qb_u = smem_u32(smem + SM_QB);
    const unsigned kb_u = smem_u32(smem + SM_KB);

    // ========== build Qb (fp32 -> bf16, swizzled 16B chunks) ==========
    // chunk swizzle: chunk' = chunk ^ (row & 7)  (16 chunks of 16 B per row)
    #pragma unroll
    for (int it = 0; it < 8; ++it) {
        int ci = it * 256 + tid;        // 0..2047
        int r = ci >> 4, ch = ci & 15;
        const float* gp = Qg + (size_t)r * DIM + ch * 8;
        float4 f0 = *(const float4*)gp;
        float4 f1 = *(const float4*)(gp + 4);
        uint4 u;
        u.x = cvt2bf(f0.x, f0.y); u.y = cvt2bf(f0.z, f0.w);
        u.z = cvt2bf(f1.x, f1.y); u.w = cvt2bf(f1.z, f1.w);
        *(uint4*)(smem + SM_QB + r * 256 + ((ch ^ (r & 7)) << 4)) = u;
    }

    // ---- K tile 0: load + convert into regs, store (own slots) ----
    uint4 kc[4];
    #pragma unroll
    for (int it = 0; it < 4; ++it) {
        int ci = it * 256 + tid;        // 0..1023
        int r = ci >> 4, ch = ci & 15;
        const float* gp = Kg + (size_t)r * DIM + ch * 8;
        float4 f0 = *(const float4*)gp;
        float4 f1 = *(const float4*)(gp + 4);
        kc[it].x = cvt2bf(f0.x, f0.y); kc[it].y = cvt2bf(f0.z, f0.w);
        kc[it].z = cvt2bf(f1.x, f1.y); kc[it].w = cvt2bf(f1.z, f1.w);
    }
    #pragma unroll
    for (int it = 0; it < 4; ++it) {
        int ci = it * 256 + tid;
        int r = ci >> 4, ch = ci & 15;
        *(uint4*)(smem + SM_KB + r * 256 + ((ch ^ (r & 7)) << 4)) = kc[it];
    }

    // ---- per-lane ldmatrix addresses ----
    // swizzled chunk for (row, chunk=2*kk+dc): since row%8 == lane%8 for all our
    // groups, chunk' = ((kk ^ (xr>>1))<<1) | (dc ^ (xr&1)) with xr = lane&7.
    const int xr  = lane & 7;
    const int xh  = xr >> 1;
    const int a_row = w * 16 + ((lane >> 3) & 1) * 8 + xr;   // Q row (global in tile)
    const int a_dc  = (lane >> 4) & 1;                       // +8 d for matrices 2,3
    const unsigned a_base2 = qb_u + a_row * 256 + ((a_dc ^ (xr & 1)) << 4);
    const int b_row = ((lane >> 4) & 1) * 8 + xr;            // key row offset in jp pair
    const int b_dc  = (lane >> 3) & 1;
    const unsigned b_base2 = kb_u + b_row * 256 + ((b_dc ^ (xr & 1)) << 4);

    // softmax state: this thread co-owns rows q_r0 (c0,c1) and q_r1 (c2,c3)
    const int q_r0 = w * 16 + (lane >> 2);
    const int q_r1 = q_r0 + 8;
    float* S0 = Srow + (size_t)q_r0 * LK + 2 * (lane & 3);
    float* S1 = Srow + (size_t)q_r1 * LK + 2 * (lane & 3);
    float m_a = -INFINITY, z_a = 0.f, m_b = -INFINITY, z_b = 0.f;

    // ================= pass 1: tensor-core QK^T, spill S, online (m,Z) ========
    for (int k0 = 0; k0 < LK; k0 += BKT) {
        __syncthreads();                 // Kb (and first-iter Qb) stores visible

        const bool hn = (k0 + BKT) < LK;
        if (hn) {
            const float* Kn = Kg + (size_t)(k0 + BKT) * DIM;
            #pragma unroll
            for (int it = 0; it < 4; ++it) {
                int ci = it * 256 + tid;
                int r = ci >> 4, ch = ci & 15;
                const float* gp = Kn + (size_t)r * DIM + ch * 8;
                float4 f0 = *(const float4*)gp;
                float4 f1 = *(const float4*)(gp + 4);
                kc[it].x = cvt2bf(f0.x, f0.y); kc[it].y = cvt2bf(f0.z, f0.w);
                kc[it].z = cvt2bf(f1.x, f1.y); kc[it].w = cvt2bf(f1.z, f1.w);
            }
        }

        float s[8][4];
        #pragma unroll
        for (int j = 0; j < 8; ++j)
            #pragma unroll
            for (int i = 0; i < 4; ++i) s[j][i] = 0.f;

        #pragma unroll
        for (int kk = 0; kk < 8; ++kk) {               // 16-d steps
            unsigned a0, a1, a2, a3;
            LDSM_X4(a0, a1, a2, a3, a_base2 + ((kk ^ xh) << 5));
            #pragma unroll
            for (int jp = 0; jp < 4; ++jp) {           // 2 n-tiles per ldmatrix.x4
                unsigned b0, b1, b2, b3;
                LDSM_X4(b0, b1, b2, b3, b_base2 + jp * 4096 + ((kk ^ xh) << 5));
                MMA_BF16(s[2*jp],   a0, a1, a2, a3, b0, b1);
                MMA_BF16(s[2*jp+1], a0, a1, a2, a3, b2, b3);
            }
        }

        // epilogue: S = -acc*scale; spill; online (m,Z) per row via quad shfl
        float tm0 = -INFINITY, tm1 = -INFINITY;
        #pragma unroll
        for (int j = 0; j < 8; ++j) {
            s[j][0] = -s[j][0] * scale;  s[j][1] = -s[j][1] * scale;
            s[j][2] = -s[j][2] * scale;  s[j][3] = -s[j][3] * scale;
            tm0 = fmaxf(tm0, fmaxf(s[j][0], s[j][1]));
            tm1 = fmaxf(tm1, fmaxf(s[j][2], s[j][3]));
            *(float2*)(S0 + k0 + 8*j) = make_float2(s[j][0], s[j][1]);
            *(float2*)(S1 + k0 + 8*j) = make_float2(s[j][2], s[j][3]);
        }
        tm0 = fmaxf(tm0, __shfl_xor_sync(0xffffffffu, tm0, 1));
        tm0 = fmaxf(tm0, __shfl_xor_sync(0xffffffffu, tm0, 2));
        tm1 = fmaxf(tm1, __shfl_xor_sync(0xffffffffu, tm1, 1));
        tm1 = fmaxf(tm1, __shfl_xor_sync(0xffffffffu, tm1, 2));
        float nm0 = fmaxf(m_a, tm0), nm1 = fmaxf(m_b, tm1);
        float ss0 = 0.f, ss1 = 0.f;
        #pragma unroll
        for (int j = 0; j < 8; ++j) {
            ss0 += __expf(s[j][0] - nm0) + __expf(s[j][1] - nm0);
            ss1 += __expf(s[j][2] - nm1) + __expf(s[j][3] - nm1);
        }
        ss0 += __shfl_xor_sync(0xffffffffu, ss0, 1);
        ss0 += __shfl_xor_sync(0xffffffffu, ss0, 2);
        ss1 += __shfl_xor_sync(0xffffffffu, ss1, 1);
        ss1 += __shfl_xor_sync(0xffffffffu, ss1, 2);
        z_a = z_a * __expf(m_a - nm0) + ss0;  m_a = nm0;
        z_b = z_b * __expf(m_b - nm1) + ss1;  m_b = nm1;

        __syncthreads();                 // all Kb/Qb reads of this tile done
        if (hn) {
            #pragma unroll
            for (int it = 0; it < 4; ++it) {
                int ci = it * 256 + tid;
                int r = ci >> 4, ch = ci & 15;
                *(uint4*)(smem + SM_KB + r * 256 + ((ch ^ (r & 7)) << 4)) = kc[it];
            }
        }
    }

    // hand off per-row stats (quad lane 0 writes; 8 warps cover 128 rows)
    if ((lane & 3) == 0) {
        row_m[q_r0] = m_a;  row_z[q_r0] = z_a;
        row_m[q_r1] = m_b;  row_z[q_r1] = z_b;
    }
    __syncthreads();        // row_m/z visible; pass-1 smem reads closed

    // ================= pass 2: E = exp(-g*p), Z2, O = E V  (unchanged SIMT) ====
    const int ty = tid >> 4;   // 0..15 -> 8 query rows each
    const int tx = tid & 15;   // 0..15 -> 4 key cols (E) / 8 d cols (PV)

    float m1[8], invZ1[8];
    #pragma unroll
    for (int i = 0; i < 8; ++i) {
        m1[i]    = row_m[ty * 8 + i];
        invZ1[i] = 1.f / row_z[ty * 8 + i];
    }

    int ld_r[TILE_LD_ITERS], ld_c[TILE_LD_ITERS];
    #pragma unroll
    for (int it = 0; it < TILE_LD_ITERS; ++it) {
        int idx = tid * 4 + it * NTHR * 4;
        ld_r[it] = idx >> 7; ld_c[it] = idx & 127;
    }

    unsigned long long o2[8][4];
    #pragma unroll
    for (int i = 0; i < 8; i++)
        #pragma unroll
        for (int j = 0; j < 4; j++) o2[i][j] = 0ull;
    float Z2[8];
    #pragma unroll
    for (int i = 0; i < 8; i++) Z2[i] = 0.f;

    float4 vbuf[TILE_LD_ITERS];
    #pragma unroll
    for (int it = 0; it < TILE_LD_ITERS; ++it)
        vbuf[it] = *(const float4*)(Vg + (size_t)ld_r[it] * DIM + ld_c[it]);
    #pragma unroll
    for (int it = 0; it < TILE_LD_ITERS; ++it)
        *(float4*)(Vs + ld_r[it] * VS_STRIDE + ld_c[it]) = vbuf[it];

    for (int k0 = 0; k0 < LK; k0 += BKT) {
        const bool has_next = (k0 + BKT) < LK;
        if (has_next) {
            const float* Vn = Vg + (size_t)(k0 + BKT) * DIM;
            #pragma unroll
            for (int it = 0; it < TILE_LD_ITERS; ++it)
                vbuf[it] = *(const float4*)(Vn + (size_t)ld_r[it] * DIM + ld_c[it]);
        }

        // E tile: p = exp(S - m1)/Z1 ; E = exp(-g*p)   (T = -g*p in (-1,0])
        #pragma unroll
        for (int i = 0; i < 8; i++) {
            int r = ty * 8 + i;
            float4 sv = *(const float4*)(Srow + (size_t)r * LK + k0 + tx*4);
            float4 gv = *(const float4*)(Grow + (size_t)r * LK + k0 + tx*4);
            float s[4] = {sv.x, sv.y, sv.z, sv.w};
            float g[4] = {gv.x, gv.y, gv.z, gv.w};
            float e[4];
            #pragma unroll
            for (int j = 0; j < 4; j++) {
                float p = __expf(s[j] - m1[i]) * invZ1[i];
                e[j] = __expf(-g[j] * p);
                Z2[i] += e[j];
            }
            *(float4*)(Es + r * ES_STRIDE + tx * 4) = make_float4(e[0], e[1], e[2], e[3]);
        }
        __syncthreads();    // Vs stores + Es writes visible

        // PV: o[i][:] += E[row_i][k] * V[k][:]   (8x8 per thread, f32x2)
        #pragma unroll 2
        for (int k = 0; k < BKT; k += 4) {
            float4 e4[8];
            #pragma unroll
            for (int i = 0; i < 8; i++) e4[i] = *(const float4*)(Es + (ty*8+i)*ES_STRIDE + k);
            #pragma unroll
            for (int kk = 0; kk < 4; kk++) {
                ulonglong2 v0 = *(const ulonglong2*)(Vs + (k + kk) * VS_STRIDE + tx * 8);
                ulonglong2 v1 = *(const ulonglong2*)(Vs + (k + kk) * VS_STRIDE + tx * 8 + 4);
                #pragma unroll
                for (int i = 0; i < 8; i++) {
                    float e = (kk == 0) ? e4[i].x : (kk == 1) ? e4[i].y
                            : (kk == 2) ? e4[i].z : e4[i].w;
                    unsigned long long ee = pack2(e, e);
                    FFMA2(o2[i][0], ee, v0.x);
                    FFMA2(o2[i][1], ee, v0.y);
                    FFMA2(o2[i][2], ee, v1.x);
                    FFMA2(o2[i][3], ee, v1.y);
                }
            }
        }

        __syncthreads();    // all Vs/Es reads of this tile done
        if (has_next) {
            #pragma unroll
            for (int it = 0; it < TILE_LD_ITERS; ++it)
                *(float4*)(Vs + ld_r[it] * VS_STRIDE + ld_c[it]) = vbuf[it];
        }
    }

    // ---- finalize: reduce Z2 across tx half-warp, write O / Z2 ----
    #pragma unroll
    for (int i = 0; i < 8; i++) {
        float z = Z2[i];
        #pragma unroll
        for (int off = 8; off > 0; off >>= 1)
            z += __shfl_xor_sync(0xffffffffu, z, off);
        float rz = 1.f / z;
        float ov[8];
        #pragma unroll
        for (int jp = 0; jp < 4; jp++) unpack2(o2[i][jp], ov[2*jp], ov[2*jp+1]);
        float* outr = Op + ((size_t)b * LQ + q0 + ty * 8 + i) * DIM + tx * 8;
        *(float4*)(outr)     = make_float4(ov[0]*rz, ov[1]*rz, ov[2]*rz, ov[3]*rz);
        *(float4*)(outr + 4) = make_float4(ov[4]*rz, ov[5]*rz, ov[6]*rz, ov[7]*rz);
    }
}

extern "C" void kernel_launch(void* const* d_in, const int* in_sizes, int n_in,
                              void* d_out, int out_size)
{
    const float* Q  = (const float*)d_in[0];
    const float* K  = (const float*)d_in[1];
    const float* V  = (const float*)d_in[2];
    const float* sc = (const float*)d_in[3];
    const float* G  = (const float*)d_in[4];
    float* Out = (float*)d_out;

    cudaFuncSetAttribute(attn_neg2sm_kernel,
                         cudaFuncAttributeMaxDynamicSharedMemorySize, SMEM_BYTES);

    dim3 grid(LQ / BM, BATCH);   // 16 x 16 = 256 CTAs
    attn_neg2sm_kernel<<<grid, NTHR, SMEM_BYTES>>>(Q, K, V, sc, G, Out);
}